// round 8
// baseline (speedup 1.0000x reference)
#include <cuda_runtime.h>
#include <cuda_bf16.h>
#include <cuda_fp8.h>
#include <cstdint>

#define BATCH 4096
#define NVIEW 2
#define DIM   512
#define NTOT  8192
#define NCLS  1000

#define C_EXP  20.60992915555662f   // log2(e)/0.07
#define INV_T  14.285714285714286f  // 1/0.07
#define EBIAS  10.0f
#define ESCALE 1024.0f              // 2^EBIAS

// ---------------- smem layout (bytes) ----------------
#define A_STRIDE   528                 // 512 fp8 + 16 pad (132 words; 4-word/row bank step -> conflict-free)
#define A_BYTES    (128 * A_STRIDE)    // 67584
#define B_STRIDE   272                 // 256 fp8 + 16 pad
#define B_STAGE    (128 * B_STRIDE)    // 34816
#define OFF_A      0
#define OFF_B      A_BYTES
#define OFF_RED    (OFF_B + 3 * B_STAGE)      // 172032
#define OFF_MBAR   (OFF_RED + 4 * 128 * 4)    // 174080  full[3] then empty[3]
#define SMEM_TOTAL (OFF_MBAR + 48)            // 174128

// ---------------- scratch ----------------
__device__ __align__(16) __nv_bfloat16 g_A[(size_t)NTOT * DIM];
__device__ __align__(16) uint8_t       g_A8[(size_t)NTOT * DIM];
__device__ __align__(16) float         g_Ssum[NCLS * DIM];
__device__ float g_Z[NTOT];
__device__ float g_sum;
__device__ int   g_cnt[NCLS];

// ---------------- PTX helpers ----------------
__device__ __forceinline__ void ldm4(uint32_t r[4], uint32_t addr) {
    asm volatile("ldmatrix.sync.aligned.m8n8.x4.shared.b16 {%0,%1,%2,%3}, [%4];"
        : "=r"(r[0]), "=r"(r[1]), "=r"(r[2]), "=r"(r[3]) : "r"(addr));
}
__device__ __forceinline__ void qmma(float c[4], const uint32_t a[4], const uint32_t b[2]) {
    asm volatile("mma.sync.aligned.m16n8k32.row.col.f32.e4m3.e4m3.f32 "
        "{%0,%1,%2,%3}, {%4,%5,%6,%7}, {%8,%9}, {%0,%1,%2,%3};"
        : "+f"(c[0]), "+f"(c[1]), "+f"(c[2]), "+f"(c[3])
        : "r"(a[0]), "r"(a[1]), "r"(a[2]), "r"(a[3]), "r"(b[0]), "r"(b[1]));
}
__device__ __forceinline__ uint32_t smem_u32(const void* p) {
    uint32_t a;
    asm("{ .reg .u64 t; cvta.to.shared.u64 t, %1; cvt.u32.u64 %0, t; }" : "=r"(a) : "l"(p));
    return a;
}
__device__ __forceinline__ void bulk_cp(uint32_t dst, const void* src, uint32_t bytes, uint32_t mbar) {
    asm volatile("cp.async.bulk.shared::cta.global.mbarrier::complete_tx::bytes [%0], [%1], %2, [%3];"
        :: "r"(dst), "l"(src), "r"(bytes), "r"(mbar) : "memory");
}
__device__ __forceinline__ void mbar_init(uint32_t mbar, uint32_t cnt) {
    asm volatile("mbarrier.init.shared.b64 [%0], %1;" :: "r"(mbar), "r"(cnt) : "memory");
}
__device__ __forceinline__ void mbar_expect(uint32_t mbar, uint32_t bytes) {
    asm volatile("mbarrier.arrive.expect_tx.shared.b64 _, [%0], %1;" :: "r"(mbar), "r"(bytes) : "memory");
}
__device__ __forceinline__ void mbar_arrive(uint32_t mbar) {
    asm volatile("mbarrier.arrive.release.cta.shared.b64 _, [%0];" :: "r"(mbar) : "memory");
}
__device__ __forceinline__ void mbar_wait(uint32_t mbar, uint32_t parity) {
    uint32_t done;
    asm volatile("{ .reg .pred p; mbarrier.try_wait.parity.acquire.cta.shared::cta.b64 p, [%1], %2; selp.b32 %0, 1, 0, p; }"
        : "=r"(done) : "r"(mbar), "r"(parity) : "memory");
    if (!done) {
        asm volatile("{ .reg .pred P1;\n"
            "W_%=: mbarrier.try_wait.parity.acquire.cta.shared::cta.b64 P1, [%0], %1, 0x989680;\n"
            "@P1 bra.uni D_%=;\n bra.uni W_%=;\n D_%=: }"
            :: "r"(mbar), "r"(parity) : "memory");
    }
}
__device__ __forceinline__ uint32_t pack_h2(float lo, float hi) {
    uint32_t h;
    asm("cvt.rn.f16x2.f32 %0, %1, %2;" : "=r"(h) : "f"(hi), "f"(lo));
    return h;
}
__device__ __forceinline__ uint32_t ex2_h2(uint32_t x) {
    uint32_t e;
    asm("ex2.approx.f16x2 %0, %1;" : "=r"(e) : "r"(x));
    return e;
}
__device__ __forceinline__ uint32_t hadd2(uint32_t a, uint32_t b) {
    uint32_t d;
    asm("add.rn.f16x2 %0, %1, %2;" : "=r"(d) : "r"(a), "r"(b));
    return d;
}
__device__ __forceinline__ float2 h2_to_f2(uint32_t h) {
    float lo, hi;
    asm("{ .reg .f16 l, hh; mov.b32 {l, hh}, %2; cvt.f32.f16 %0, l; cvt.f32.f16 %1, hh; }"
        : "=f"(lo), "=f"(hi) : "r"(h));
    return make_float2(lo, hi);
}

// ------------------------- kernel 1: normalize + view-swap -> bf16 + fp8 (+zero accumulators) -------------------------
__global__ void norm_kernel(const float* __restrict__ feats) {
    int warp = threadIdx.x >> 5, lane = threadIdx.x & 31;
    int row  = blockIdx.x * 8 + warp;
    int b = row & (BATCH - 1);
    int v = row >> 12;
    if (blockIdx.x == 0 && threadIdx.x == 0) g_sum = 0.f;
    const float4* src = reinterpret_cast<const float4*>(feats + (size_t)(b * NVIEW + v) * DIM);
    float4 f[4];
    float ss = 0.f;
#pragma unroll
    for (int q = 0; q < 4; q++) {
        f[q] = src[lane + 32 * q];
        ss += f[q].x * f[q].x + f[q].y * f[q].y + f[q].z * f[q].z + f[q].w * f[q].w;
    }
#pragma unroll
    for (int o = 16; o; o >>= 1) ss += __shfl_xor_sync(0xffffffffu, ss, o);
    float sc = 1.0f / fmaxf(sqrtf(ss), 1e-8f);
    if (lane == 0) g_Z[row] = 0.f;
    uint2* dst = reinterpret_cast<uint2*>(g_A + (size_t)row * DIM);
    uint32_t* dst8 = reinterpret_cast<uint32_t*>(g_A8 + (size_t)row * DIM);
#pragma unroll
    for (int q = 0; q < 4; q++) {
        float x = f[q].x * sc, y = f[q].y * sc, z = f[q].z * sc, w = f[q].w * sc;
        __nv_bfloat162 p0 = __floats2bfloat162_rn(x, y);
        __nv_bfloat162 p1 = __floats2bfloat162_rn(z, w);
        uint2 pk;
        pk.x = *reinterpret_cast<uint32_t*>(&p0);
        pk.y = *reinterpret_cast<uint32_t*>(&p1);
        dst[lane + 32 * q] = pk;
        __nv_fp8x2_storage_t lo = __nv_cvt_float2_to_fp8x2(make_float2(x, y), __NV_SATFINITE, __NV_E4M3);
        __nv_fp8x2_storage_t hi = __nv_cvt_float2_to_fp8x2(make_float2(z, w), __NV_SATFINITE, __NV_E4M3);
        dst8[lane + 32 * q] = (uint32_t)lo | ((uint32_t)hi << 16);
    }
}

// ------------------------- kernel 2: per-class feature sums + counts (deterministic) -------------------------
__global__ void class_sum(const int* __restrict__ labels) {
    const int cls = blockIdx.x;
    const int t = threadIdx.x, lane = t & 31;
    __shared__ int list[160];
    __shared__ int ncnt;
    if (t < 32) {
        int n = 0;
        for (int base = 0; base < BATCH; base += 32) {
            int lb = labels[base + lane];
            unsigned bal = __ballot_sync(0xffffffffu, lb == cls);
            if (lb == cls) {
                int pos = n + __popc(bal & ((1u << lane) - 1));
                if (pos < 160) list[pos] = base + lane;
            }
            n += __popc(bal);
        }
        if (lane == 0) { g_cnt[cls] = n; ncnt = (n < 160) ? n : 160; }
    }
    __syncthreads();
    const int n = ncnt;
    const int d = t * 4;
    float4 acc = make_float4(0.f, 0.f, 0.f, 0.f);
    for (int k = 0; k < n; k++) {
        int b = list[k];
#pragma unroll
        for (int v = 0; v < 2; v++) {
            const uint2 u = *reinterpret_cast<const uint2*>(g_A + (size_t)(v * BATCH + b) * DIM + d);
            float2 a0 = __bfloat1622float2(*reinterpret_cast<const __nv_bfloat162*>(&u.x));
            float2 a1 = __bfloat1622float2(*reinterpret_cast<const __nv_bfloat162*>(&u.y));
            acc.x += a0.x; acc.y += a0.y; acc.z += a1.x; acc.w += a1.y;
        }
    }
    *reinterpret_cast<float4*>(g_Ssum + cls * DIM + d) = acc;
}

// ------------------------- kernel 3: fp8 GEMM upper triangle, barrier-free pipeline -------------------------
__global__ void __launch_bounds__(512, 1) supcon_main() {
    extern __shared__ char smem[];
    const int t = threadIdx.x, lane = t & 31, wid = t >> 5;
    const int warp_m = wid >> 2, warp_n = wid & 3;      // 4 x 4 warps, 32x32 tiles
    const int iblk = blockIdx.x;                         // row block 0..63
    const int sseg = blockIdx.y;                         // c-range segment 0..1
    const int row_base = iblk * 128;
    const int cbase = sseg ? 17 : 0;
    const int cend  = sseg ? ((iblk < 32) ? 33 : 32) : 17;   // exclusive
    const int NTILE = cend - cbase;
    const int NCHUNK = 2 * NTILE;
    const uint32_t sbase = smem_u32(smem);
    const uint32_t mbf = sbase + OFF_MBAR;        // full[3]
    const uint32_t mbe = sbase + OFF_MBAR + 24;   // empty[3]

    if (t < 3) { mbar_init(mbf + t * 8, 1); mbar_init(mbe + t * 8, 16); }

    // full-K A tile (128 rows x 512 fp8), padded stride
    for (int f = t; f < 4096; f += 512) {
        int row = f >> 5, seg = f & 31;
        uint4 v = *reinterpret_cast<const uint4*>(g_A8 + (size_t)(row_base + row) * DIM + seg * 16);
        *reinterpret_cast<uint4*>(smem + OFF_A + row * A_STRIDE + seg * 16) = v;
    }
    __syncthreads();   // A visible + mbars initialized

    // prologue: warp 0 loads chunks 0,1,2 (K=256 half-tiles)
    if (wid == 0) {
#pragma unroll
        for (int p = 0; p < 3; p++) {
            const int jb = (iblk + cbase + (p >> 1)) & 63;
            const uint8_t* src = g_A8 + (size_t)jb * (128 * DIM) + (p & 1) * 256;
            if (lane == 0) mbar_expect(mbf + p * 8, 32768);
            __syncwarp();
#pragma unroll
            for (int r = 0; r < 4; r++) {
                const int row = lane * 4 + r;
                bulk_cp(sbase + OFF_B + p * B_STAGE + row * B_STRIDE,
                        src + (size_t)row * DIM, 256, mbf + p * 8);
            }
        }
    }

    const uint32_t abase = sbase + OFF_A + (warp_m * 32 + (lane & 15)) * A_STRIDE + (lane >> 4) * 16;
    const uint32_t bb_lane = (((lane & 7) + ((lane >> 4) & 1) * 8) + warp_n * 32) * B_STRIDE + ((lane >> 3) & 1) * 16;

    float acc[2][4][4];
#pragma unroll
    for (int m = 0; m < 2; m++)
#pragma unroll
        for (int n = 0; n < 4; n++)
#pragma unroll
            for (int r = 0; r < 4; r++) acc[m][n][r] = 0.f;
    float z[4] = {0.f, 0.f, 0.f, 0.f};

    for (int cc = 0; cc < NCHUNK; cc++) {
        const int s = cc % 3;
        const uint32_t ph = (uint32_t)(cc / 3) & 1u;
        mbar_wait(mbf + s * 8, ph);

        const uint32_t bb = sbase + OFF_B + s * B_STAGE + bb_lane;
        const int ch = cc & 1;
#pragma unroll
        for (int ks = 0; ks < 8; ks++) {
            const int koff = ks * 32;
            uint32_t a[2][4];
            ldm4(a[0], abase + (ch * 256 + koff));
            ldm4(a[1], abase + 16 * A_STRIDE + (ch * 256 + koff));
            uint32_t b[4][2];
#pragma unroll
            for (int p = 0; p < 2; p++) {
                uint32_t r4[4];
                ldm4(r4, bb + p * (16 * B_STRIDE) + koff);
                b[2 * p][0] = r4[0]; b[2 * p][1] = r4[1];
                b[2 * p + 1][0] = r4[2]; b[2 * p + 1][1] = r4[3];
            }
#pragma unroll
            for (int m = 0; m < 2; m++)
#pragma unroll
                for (int n = 0; n < 4; n++) qmma(acc[m][n], a[m], b[n]);
        }
        if (lane == 0) mbar_arrive(mbe + s * 8);   // this warp done reading chunk cc

        // producer: refill slot s with chunk cc+3 once all 16 warps are done with cc
        if (wid == 0 && cc + 3 < NCHUNK) {
            mbar_wait(mbe + s * 8, ph);
            const int nc = cc + 3;
            const int jb = (iblk + cbase + (nc >> 1)) & 63;
            const uint8_t* src = g_A8 + (size_t)jb * (128 * DIM) + (nc & 1) * 256;
            if (lane == 0) mbar_expect(mbf + s * 8, 32768);
            __syncwarp();
#pragma unroll
            for (int r = 0; r < 4; r++) {
                const int row = lane * 4 + r;
                bulk_cp(sbase + OFF_B + s * B_STAGE + row * B_STRIDE,
                        src + (size_t)row * DIM, 256, mbf + s * 8);
            }
        }

        if (ch) {   // tile j = cc>>1 complete -> epilogue (register-only inputs)
            const int ctile = cbase + (cc >> 1);
            const int jblk = (iblk + ctile) & 63;
            const bool dg = (ctile == 0);
            uint32_t zh[4] = {0, 0, 0, 0};
            uint32_t csh[4] = {0, 0, 0, 0};
#pragma unroll
            for (int m = 0; m < 2; m++)
#pragma unroll
                for (int n = 0; n < 4; n++)
#pragma unroll
                    for (int h = 0; h < 2; h++) {
                        float x0 = acc[m][n][2 * h]     * C_EXP - EBIAS;
                        float x1 = acc[m][n][2 * h + 1] * C_EXP - EBIAS;
                        if (dg) {
                            int rl = warp_m * 32 + m * 16 + h * 8 + (lane >> 2);
                            int cl0 = warp_n * 32 + n * 8 + (lane & 3) * 2;
                            if (rl == cl0)     x0 = -60.f;
                            if (rl == cl0 + 1) x1 = -60.f;
                        }
                        uint32_t e2 = ex2_h2(pack_h2(x0, x1));
                        zh[2 * m + h] = hadd2(zh[2 * m + h], e2);
                        csh[n] = hadd2(csh[n], e2);
                        acc[m][n][2 * h] = 0.f; acc[m][n][2 * h + 1] = 0.f;
                    }
#pragma unroll
            for (int g = 0; g < 4; g++) {
                float2 f = h2_to_f2(zh[g]);
                z[g] += f.x + f.y;
            }
            if (!dg) {
#pragma unroll
                for (int n = 0; n < 4; n++) {
                    uint32_t v = csh[n];
                    v = hadd2(v, __shfl_xor_sync(0xffffffffu, v, 4));
                    v = hadd2(v, __shfl_xor_sync(0xffffffffu, v, 8));
                    v = hadd2(v, __shfl_xor_sync(0xffffffffu, v, 16));
                    csh[n] = v;
                }
                if (lane < 4) {
                    float* zj = &g_Z[jblk * 128 + warp_n * 32 + lane * 2];
#pragma unroll
                    for (int n = 0; n < 4; n++) {
                        float2 f = h2_to_f2(csh[n]);
                        atomicAdd(&zj[n * 8 + 0], f.x * ESCALE);
                        atomicAdd(&zj[n * 8 + 1], f.y * ESCALE);
                    }
                }
            }
        }
    }

    // row z: reduce over quad lanes, then across warp_n via smem
#pragma unroll
    for (int g = 0; g < 4; g++) {
        z[g] += __shfl_xor_sync(0xffffffffu, z[g], 1);
        z[g] += __shfl_xor_sync(0xffffffffu, z[g], 2);
    }
    float* red = reinterpret_cast<float*>(smem + OFF_RED);   // [4][128]
    __syncthreads();
    if ((lane & 3) == 0) {
        int g4 = lane >> 2;
#pragma unroll
        for (int m = 0; m < 2; m++)
#pragma unroll
            for (int h = 0; h < 2; h++) {
                int rl = warp_m * 32 + m * 16 + h * 8 + g4;
                red[warp_n * 128 + rl] = z[2 * m + h];
            }
    }
    __syncthreads();
    if (t < 128)
        atomicAdd(&g_Z[row_base + t],
                  (red[t] + red[128 + t] + red[256 + t] + red[384 + t]) * ESCALE);
}

// ------------------------- kernel 4: per-row loss, block-reduced into g_sum -------------------------
__global__ void finalize1(const int* __restrict__ labels) {
    __shared__ float wsum[8];
    const int t = threadIdx.x, lane = t & 31, wid = t >> 5;
    const int row = blockIdx.x * 8 + wid;
    const int b = row & (BATCH - 1);
    const int cls = labels[b];
    const uint2* arow = reinterpret_cast<const uint2*>(g_A) + (size_t)row * 128;
    const float4* srow = reinterpret_cast<const float4*>(g_Ssum) + (size_t)cls * 128;
    float dot = 0.f, self = 0.f;
#pragma unroll
    for (int q = 0; q < 4; q++) {
        uint2 u = arow[lane + 32 * q];
        float4 s = srow[lane + 32 * q];
        float2 a0 = __bfloat1622float2(*reinterpret_cast<const __nv_bfloat162*>(&u.x));
        float2 a1 = __bfloat1622float2(*reinterpret_cast<const __nv_bfloat162*>(&u.y));
        dot  += a0.x * s.x + a0.y * s.y + a1.x * s.z + a1.y * s.w;
        self += a0.x * a0.x + a0.y * a0.y + a1.x * a1.x + a1.y * a1.y;
    }
#pragma unroll
    for (int o = 16; o; o >>= 1) {
        dot  += __shfl_xor_sync(0xffffffffu, dot, o);
        self += __shfl_xor_sync(0xffffffffu, self, o);
    }
    if (lane == 0) {
        float C = 2.0f * (float)g_cnt[cls] - 1.0f;
        float Z = g_Z[row];
        float S = (dot - self) * INV_T;
        wsum[wid] = (S - C * logf(Z + 1e-8f)) / (C + 1e-8f);
    }
    __syncthreads();
    if (t == 0) {
        float bs = 0.f;
#pragma unroll
        for (int w = 0; w < 8; w++) bs += wsum[w];
        atomicAdd(&g_sum, bs);
    }
}

// ------------------------- kernel 5: final scale -------------------------
__global__ void finalize2(float* __restrict__ out) {
    out[0] = -g_sum / (float)NTOT;
}

// ------------------------- launch -------------------------
extern "C" void kernel_launch(void* const* d_in, const int* in_sizes, int n_in,
                              void* d_out, int out_size) {
    const float* feats = (const float*)d_in[0];
    const int* labels = (const int*)d_in[1];
    (void)in_sizes; (void)n_in; (void)out_size;

    cudaFuncSetAttribute(supcon_main, cudaFuncAttributeMaxDynamicSharedMemorySize, SMEM_TOTAL);

    norm_kernel<<<NTOT / 8, 256>>>(feats);
    class_sum<<<NCLS, 128>>>(labels);
    supcon_main<<<dim3(64, 2), 512, SMEM_TOTAL>>>();
    finalize1<<<NTOT / 8, 256>>>(labels);
    finalize2<<<1, 1>>>((float*)d_out);
}

// round 10
// speedup vs baseline: 1.8971x; 1.8971x over previous
#include <cuda_runtime.h>
#include <cuda_bf16.h>
#include <cuda_fp8.h>
#include <cstdint>

#define BATCH 4096
#define NVIEW 2
#define DIM   512
#define NTOT  8192
#define NCLS  1000

#define C_EXP  20.60992915555662f   // log2(e)/0.07
#define INV_T  14.285714285714286f  // 1/0.07
#define EBIAS  10.0f
#define ESCALE 1024.0f              // 2^EBIAS

#define NTILES_TOTAL 2080
#define NCTA 148

// ---------------- smem layout (bytes) ----------------
#define A_STRIDE   528                 // 512 fp8 + 16 pad per row -> conflict-free ldmatrix
#define TILE_BYTES (128 * A_STRIDE)    // 67584
#define OFF_A      0
#define OFF_B      TILE_BYTES          // two full-K B stages
#define OFF_RED    (OFF_B + 2 * TILE_BYTES)   // 202752
#define OFF_MBAR   (OFF_RED + 4 * 128 * 4)    // 204800
#define SMEM_TOTAL (OFF_MBAR + 16)            // 204816

// ---------------- scratch ----------------
__device__ __align__(16) __nv_bfloat16 g_A[(size_t)NTOT * DIM];
__device__ __align__(16) uint8_t       g_A8[(size_t)NTOT * DIM];
__device__ __align__(16) float         g_Ssum[NCLS * DIM];
__device__ float g_Z[NTOT];
__device__ float g_sum;
__device__ int   g_cnt[NCLS];

// ---------------- PTX helpers ----------------
__device__ __forceinline__ void ldm4(uint32_t r[4], uint32_t addr) {
    asm volatile("ldmatrix.sync.aligned.m8n8.x4.shared.b16 {%0,%1,%2,%3}, [%4];"
        : "=r"(r[0]), "=r"(r[1]), "=r"(r[2]), "=r"(r[3]) : "r"(addr));
}
__device__ __forceinline__ void qmma(float c[4], const uint32_t a[4], const uint32_t b[2]) {
    asm volatile("mma.sync.aligned.m16n8k32.row.col.f32.e4m3.e4m3.f32 "
        "{%0,%1,%2,%3}, {%4,%5,%6,%7}, {%8,%9}, {%0,%1,%2,%3};"
        : "+f"(c[0]), "+f"(c[1]), "+f"(c[2]), "+f"(c[3])
        : "r"(a[0]), "r"(a[1]), "r"(a[2]), "r"(a[3]), "r"(b[0]), "r"(b[1]));
}
__device__ __forceinline__ uint32_t smem_u32(const void* p) {
    uint32_t a;
    asm("{ .reg .u64 t; cvta.to.shared.u64 t, %1; cvt.u32.u64 %0, t; }" : "=r"(a) : "l"(p));
    return a;
}
__device__ __forceinline__ void bulk_cp(uint32_t dst, const void* src, uint32_t bytes, uint32_t mbar) {
    asm volatile("cp.async.bulk.shared::cta.global.mbarrier::complete_tx::bytes [%0], [%1], %2, [%3];"
        :: "r"(dst), "l"(src), "r"(bytes), "r"(mbar) : "memory");
}
__device__ __forceinline__ void mbar_init(uint32_t mbar, uint32_t cnt) {
    asm volatile("mbarrier.init.shared.b64 [%0], %1;" :: "r"(mbar), "r"(cnt) : "memory");
}
__device__ __forceinline__ void mbar_expect(uint32_t mbar, uint32_t bytes) {
    asm volatile("mbarrier.arrive.expect_tx.shared.b64 _, [%0], %1;" :: "r"(mbar), "r"(bytes) : "memory");
}
__device__ __forceinline__ void mbar_wait(uint32_t mbar, uint32_t parity) {
    uint32_t done;
    asm volatile("{ .reg .pred p; mbarrier.try_wait.parity.acquire.cta.shared::cta.b64 p, [%1], %2; selp.b32 %0, 1, 0, p; }"
        : "=r"(done) : "r"(mbar), "r"(parity) : "memory");
    if (!done) {
        asm volatile("{ .reg .pred P1;\n"
            "W_%=: mbarrier.try_wait.parity.acquire.cta.shared::cta.b64 P1, [%0], %1, 0x989680;\n"
            "@P1 bra.uni D_%=;\n bra.uni W_%=;\n D_%=: }"
            :: "r"(mbar), "r"(parity) : "memory");
    }
}
__device__ __forceinline__ uint32_t pack_h2(float lo, float hi) {
    uint32_t h;
    asm("cvt.rn.f16x2.f32 %0, %1, %2;" : "=r"(h) : "f"(hi), "f"(lo));
    return h;
}
__device__ __forceinline__ uint32_t ex2_h2(uint32_t x) {
    uint32_t e;
    asm("ex2.approx.f16x2 %0, %1;" : "=r"(e) : "r"(x));
    return e;
}
__device__ __forceinline__ uint32_t hadd2(uint32_t a, uint32_t b) {
    uint32_t d;
    asm("add.rn.f16x2 %0, %1, %2;" : "=r"(d) : "r"(a), "r"(b));
    return d;
}
__device__ __forceinline__ float2 h2_to_f2(uint32_t h) {
    float lo, hi;
    asm("{ .reg .f16 l, hh; mov.b32 {l, hh}, %2; cvt.f32.f16 %0, l; cvt.f32.f16 %1, hh; }"
        : "=f"(lo), "=f"(hi) : "r"(h));
    return make_float2(lo, hi);
}
// flattened upper-triangle tile list: iblk<32 -> c in [0,33), else c in [0,32)
__device__ __forceinline__ void decode_tile(int g, int& ib, int& c) {
    if (g < 1056) { ib = g / 33; c = g - ib * 33; }
    else { int h = g - 1056; ib = 32 + (h >> 5); c = h & 31; }
}

// ------------------------- kernel 1: normalize + view-swap -> bf16 + fp8 (+zero accumulators) -------------------------
__global__ void norm_kernel(const float* __restrict__ feats) {
    int warp = threadIdx.x >> 5, lane = threadIdx.x & 31;
    int row  = blockIdx.x * 8 + warp;
    int b = row & (BATCH - 1);
    int v = row >> 12;
    if (blockIdx.x == 0 && threadIdx.x == 0) g_sum = 0.f;
    const float4* src = reinterpret_cast<const float4*>(feats + (size_t)(b * NVIEW + v) * DIM);
    float4 f[4];
    float ss = 0.f;
#pragma unroll
    for (int q = 0; q < 4; q++) {
        f[q] = src[lane + 32 * q];
        ss += f[q].x * f[q].x + f[q].y * f[q].y + f[q].z * f[q].z + f[q].w * f[q].w;
    }
#pragma unroll
    for (int o = 16; o; o >>= 1) ss += __shfl_xor_sync(0xffffffffu, ss, o);
    float sc = 1.0f / fmaxf(sqrtf(ss), 1e-8f);
    if (lane == 0) g_Z[row] = 0.f;
    uint2* dst = reinterpret_cast<uint2*>(g_A + (size_t)row * DIM);
    uint32_t* dst8 = reinterpret_cast<uint32_t*>(g_A8 + (size_t)row * DIM);
#pragma unroll
    for (int q = 0; q < 4; q++) {
        float x = f[q].x * sc, y = f[q].y * sc, z = f[q].z * sc, w = f[q].w * sc;
        __nv_bfloat162 p0 = __floats2bfloat162_rn(x, y);
        __nv_bfloat162 p1 = __floats2bfloat162_rn(z, w);
        uint2 pk;
        pk.x = *reinterpret_cast<uint32_t*>(&p0);
        pk.y = *reinterpret_cast<uint32_t*>(&p1);
        dst[lane + 32 * q] = pk;
        __nv_fp8x2_storage_t lo = __nv_cvt_float2_to_fp8x2(make_float2(x, y), __NV_SATFINITE, __NV_E4M3);
        __nv_fp8x2_storage_t hi = __nv_cvt_float2_to_fp8x2(make_float2(z, w), __NV_SATFINITE, __NV_E4M3);
        dst8[lane + 32 * q] = (uint32_t)lo | ((uint32_t)hi << 16);
    }
}

// ------------------------- kernel 2: per-class feature sums + counts (deterministic) -------------------------
__global__ void class_sum(const int* __restrict__ labels) {
    const int cls = blockIdx.x;
    const int t = threadIdx.x, lane = t & 31;
    __shared__ int list[160];
    __shared__ int ncnt;
    if (t < 32) {
        int n = 0;
        for (int base = 0; base < BATCH; base += 32) {
            int lb = labels[base + lane];
            unsigned bal = __ballot_sync(0xffffffffu, lb == cls);
            if (lb == cls) {
                int pos = n + __popc(bal & ((1u << lane) - 1));
                if (pos < 160) list[pos] = base + lane;
            }
            n += __popc(bal);
        }
        if (lane == 0) { g_cnt[cls] = n; ncnt = (n < 160) ? n : 160; }
    }
    __syncthreads();
    const int n = ncnt;
    const int d = t * 4;
    float4 acc = make_float4(0.f, 0.f, 0.f, 0.f);
    for (int k = 0; k < n; k++) {
        int b = list[k];
#pragma unroll
        for (int v = 0; v < 2; v++) {
            const uint2 u = *reinterpret_cast<const uint2*>(g_A + (size_t)(v * BATCH + b) * DIM + d);
            float2 a0 = __bfloat1622float2(*reinterpret_cast<const __nv_bfloat162*>(&u.x));
            float2 a1 = __bfloat1622float2(*reinterpret_cast<const __nv_bfloat162*>(&u.y));
            acc.x += a0.x; acc.y += a0.y; acc.z += a1.x; acc.w += a1.y;
        }
    }
    *reinterpret_cast<float4*>(g_Ssum + cls * DIM + d) = acc;
}

// ------------------------- kernel 3: fp8 GEMM upper triangle, flat 148-CTA schedule -------------------------
__global__ void __launch_bounds__(512, 1) supcon_main() {
    extern __shared__ char smem[];
    const int t = threadIdx.x, lane = t & 31, wid = t >> 5;
    const int warp_m = wid >> 2, warp_n = wid & 3;      // 4 x 4 warps, 32x32 tiles
    const int g0 = (NTILES_TOTAL * blockIdx.x) / NCTA;
    const int g1 = (NTILES_TOTAL * (blockIdx.x + 1)) / NCTA;
    const uint32_t sbase = smem_u32(smem);
    const uint32_t mb = sbase + OFF_MBAR;
    float* red = reinterpret_cast<float*>(smem + OFF_RED);   // [4][128]

    if (t == 0) { mbar_init(mb, 1); mbar_init(mb + 8, 1); }

    int ib0, c0;
    decode_tile(g0, ib0, c0);

    // load A tile for first iblk
    for (int f = t; f < 4096; f += 512) {
        int row = f >> 5, seg = f & 31;
        uint4 v = *reinterpret_cast<const uint4*>(g_A8 + (size_t)(ib0 * 128 + row) * DIM + seg * 16);
        *reinterpret_cast<uint4*>(smem + OFF_A + row * A_STRIDE + seg * 16) = v;
    }
    __syncthreads();   // A visible + mbars initialized

    // prologue: bulk-copy B tile of g0 into buf 0
    {
        const int jb = (ib0 + c0) & 63;
        if (t == 0) mbar_expect(mb, 128 * 512);
        if (t < 128)
            bulk_cp(sbase + OFF_B + t * A_STRIDE, g_A8 + (size_t)jb * (128 * DIM) + t * 512, 512, mb);
    }

    const uint32_t abase = sbase + OFF_A + (warp_m * 32 + (lane & 15)) * A_STRIDE + (lane >> 4) * 16;
    const uint32_t bb_lane = (((lane & 7) + ((lane >> 4) & 1) * 8) + warp_n * 32) * A_STRIDE + ((lane >> 3) & 1) * 16;

    float acc[2][4][4];
#pragma unroll
    for (int m = 0; m < 2; m++)
#pragma unroll
        for (int n = 0; n < 4; n++)
#pragma unroll
            for (int r = 0; r < 4; r++) acc[m][n][r] = 0.f;
    float z[4] = {0.f, 0.f, 0.f, 0.f};
    int cur_ib = ib0;

    for (int g = g0; g < g1; g++) {
        const int jl = g - g0;
        const int buf = jl & 1;
        int ib, c;
        decode_tile(g, ib, c);
        __syncthreads();                 // all warps done with buf^1 (tile g-1) and with old A
        if (g + 1 < g1) {
            int ibn, cn;
            decode_tile(g + 1, ibn, cn);
            const int jb = (ibn + cn) & 63;
            const uint32_t mbn = mb + 8 * (buf ^ 1);
            if (t == 0) mbar_expect(mbn, 128 * 512);
            if (t < 128)
                bulk_cp(sbase + OFF_B + (buf ^ 1) * TILE_BYTES + t * A_STRIDE,
                        g_A8 + (size_t)jb * (128 * DIM) + t * 512, 512, mbn);
        }
        if (ib != cur_ib) {
            // flush row sums for cur_ib
#pragma unroll
            for (int q = 0; q < 4; q++) {
                z[q] += __shfl_xor_sync(0xffffffffu, z[q], 1);
                z[q] += __shfl_xor_sync(0xffffffffu, z[q], 2);
            }
            if ((lane & 3) == 0) {
                int g4 = lane >> 2;
#pragma unroll
                for (int m = 0; m < 2; m++)
#pragma unroll
                    for (int h = 0; h < 2; h++)
                        red[warp_n * 128 + warp_m * 32 + m * 16 + h * 8 + g4] = z[2 * m + h];
            }
            __syncthreads();
            if (t < 128)
                atomicAdd(&g_Z[cur_ib * 128 + t],
                          (red[t] + red[128 + t] + red[256 + t] + red[384 + t]) * ESCALE);
            z[0] = z[1] = z[2] = z[3] = 0.f;
            // reload A for new iblk
            for (int f = t; f < 4096; f += 512) {
                int row = f >> 5, seg = f & 31;
                uint4 v = *reinterpret_cast<const uint4*>(g_A8 + (size_t)(ib * 128 + row) * DIM + seg * 16);
                *reinterpret_cast<uint4*>(smem + OFF_A + row * A_STRIDE + seg * 16) = v;
            }
            cur_ib = ib;
            __syncthreads();
        }
        mbar_wait(mb + 8 * buf, (jl >> 1) & 1);

        const uint32_t bb = sbase + OFF_B + buf * TILE_BYTES + bb_lane;
#pragma unroll
        for (int ks = 0; ks < 16; ks++) {
            const int koff = ks * 32;
            uint32_t a[2][4];
            ldm4(a[0], abase + koff);
            ldm4(a[1], abase + 16 * A_STRIDE + koff);
            uint32_t b[4][2];
#pragma unroll
            for (int p = 0; p < 2; p++) {
                uint32_t r4[4];
                ldm4(r4, bb + p * (16 * A_STRIDE) + koff);
                b[2 * p][0] = r4[0]; b[2 * p][1] = r4[1];
                b[2 * p + 1][0] = r4[2]; b[2 * p + 1][1] = r4[3];
            }
#pragma unroll
            for (int m = 0; m < 2; m++)
#pragma unroll
                for (int n = 0; n < 4; n++) qmma(acc[m][n], a[m], b[n]);
        }

        // ---- epilogue: f16x2 exp, row sums + REDG column sums ----
        {
            const int jblk = (ib + c) & 63;
            const bool dg = (c == 0);
            uint32_t zh[4] = {0, 0, 0, 0};
            uint32_t csh[4] = {0, 0, 0, 0};
#pragma unroll
            for (int m = 0; m < 2; m++)
#pragma unroll
                for (int n = 0; n < 4; n++)
#pragma unroll
                    for (int h = 0; h < 2; h++) {
                        float x0 = acc[m][n][2 * h]     * C_EXP - EBIAS;
                        float x1 = acc[m][n][2 * h + 1] * C_EXP - EBIAS;
                        if (dg) {
                            int rl = warp_m * 32 + m * 16 + h * 8 + (lane >> 2);
                            int cl0 = warp_n * 32 + n * 8 + (lane & 3) * 2;
                            if (rl == cl0)     x0 = -60.f;
                            if (rl == cl0 + 1) x1 = -60.f;
                        }
                        uint32_t e2 = ex2_h2(pack_h2(x0, x1));
                        zh[2 * m + h] = hadd2(zh[2 * m + h], e2);
                        csh[n] = hadd2(csh[n], e2);
                        acc[m][n][2 * h] = 0.f; acc[m][n][2 * h + 1] = 0.f;
                    }
#pragma unroll
            for (int q = 0; q < 4; q++) {
                float2 f = h2_to_f2(zh[q]);
                z[q] += f.x + f.y;
            }
            if (!dg) {
#pragma unroll
                for (int n = 0; n < 4; n++) {
                    uint32_t v = csh[n];
                    v = hadd2(v, __shfl_xor_sync(0xffffffffu, v, 4));
                    v = hadd2(v, __shfl_xor_sync(0xffffffffu, v, 8));
                    v = hadd2(v, __shfl_xor_sync(0xffffffffu, v, 16));
                    csh[n] = v;
                }
                if (lane < 4) {
                    float* zj = &g_Z[jblk * 128 + warp_n * 32 + lane * 2];
#pragma unroll
                    for (int n = 0; n < 4; n++) {
                        float2 f = h2_to_f2(csh[n]);
                        atomicAdd(&zj[n * 8 + 0], f.x * ESCALE);
                        atomicAdd(&zj[n * 8 + 1], f.y * ESCALE);
                    }
                }
            }
        }
    }

    // final flush of row sums for cur_ib
#pragma unroll
    for (int q = 0; q < 4; q++) {
        z[q] += __shfl_xor_sync(0xffffffffu, z[q], 1);
        z[q] += __shfl_xor_sync(0xffffffffu, z[q], 2);
    }
    __syncthreads();
    if ((lane & 3) == 0) {
        int g4 = lane >> 2;
#pragma unroll
        for (int m = 0; m < 2; m++)
#pragma unroll
            for (int h = 0; h < 2; h++)
                red[warp_n * 128 + warp_m * 32 + m * 16 + h * 8 + g4] = z[2 * m + h];
    }
    __syncthreads();
    if (t < 128)
        atomicAdd(&g_Z[cur_ib * 128 + t],
                  (red[t] + red[128 + t] + red[256 + t] + red[384 + t]) * ESCALE);
}

// ------------------------- kernel 4: per-row loss, block-reduced into g_sum -------------------------
__global__ void finalize1(const int* __restrict__ labels) {
    __shared__ float wsum[8];
    const int t = threadIdx.x, lane = t & 31, wid = t >> 5;
    const int row = blockIdx.x * 8 + wid;
    const int b = row & (BATCH - 1);
    const int cls = labels[b];
    const uint2* arow = reinterpret_cast<const uint2*>(g_A) + (size_t)row * 128;
    const float4* srow = reinterpret_cast<const float4*>(g_Ssum) + (size_t)cls * 128;
    float dot = 0.f, self = 0.f;
#pragma unroll
    for (int q = 0; q < 4; q++) {
        uint2 u = arow[lane + 32 * q];
        float4 s = srow[lane + 32 * q];
        float2 a0 = __bfloat1622float2(*reinterpret_cast<const __nv_bfloat162*>(&u.x));
        float2 a1 = __bfloat1622float2(*reinterpret_cast<const __nv_bfloat162*>(&u.y));
        dot  += a0.x * s.x + a0.y * s.y + a1.x * s.z + a1.y * s.w;
        self += a0.x * a0.x + a0.y * a0.y + a1.x * a1.x + a1.y * a1.y;
    }
#pragma unroll
    for (int o = 16; o; o >>= 1) {
        dot  += __shfl_xor_sync(0xffffffffu, dot, o);
        self += __shfl_xor_sync(0xffffffffu, self, o);
    }
    if (lane == 0) {
        float C = 2.0f * (float)g_cnt[cls] - 1.0f;
        float Z = g_Z[row];
        float S = (dot - self) * INV_T;
        wsum[wid] = (S - C * logf(Z + 1e-8f)) / (C + 1e-8f);
    }
    __syncthreads();
    if (t == 0) {
        float bs = 0.f;
#pragma unroll
        for (int w = 0; w < 8; w++) bs += wsum[w];
        atomicAdd(&g_sum, bs);
    }
}

// ------------------------- kernel 5: final scale -------------------------
__global__ void finalize2(float* __restrict__ out) {
    out[0] = -g_sum / (float)NTOT;
}

// ------------------------- launch -------------------------
extern "C" void kernel_launch(void* const* d_in, const int* in_sizes, int n_in,
                              void* d_out, int out_size) {
    const float* feats = (const float*)d_in[0];
    const int* labels = (const int*)d_in[1];
    (void)in_sizes; (void)n_in; (void)out_size;

    cudaFuncSetAttribute(supcon_main, cudaFuncAttributeMaxDynamicSharedMemorySize, SMEM_TOTAL);

    norm_kernel<<<NTOT / 8, 256>>>(feats);
    class_sum<<<NCLS, 128>>>(labels);
    supcon_main<<<NCTA, 512, SMEM_TOTAL>>>();
    finalize1<<<NTOT / 8, 256>>>(labels);
    finalize2<<<1, 1>>>((float*)d_out);
}